// round 3
// baseline (speedup 1.0000x reference)
#include <cuda_runtime.h>
#include <stdint.h>

#define DX 128
#define DY 128
#define DZ 128
#define VOX (DX * DY * DZ)
#define BATCH 4
#define NPTS 262144
#define PER_CLOUD (BATCH * NPTS)
#define TOTAL_PTS (2 * PER_CLOUD)
#define PTS_PER_THREAD 2
#define NTHREADS_TOTAL (TOTAL_PTS / PTS_PER_THREAD)

// ---------------------------------------------------------------------------
// Global float reductions (no-return REDG path).
// ---------------------------------------------------------------------------
__device__ __forceinline__ void red4(float* p, float a, float b, float c, float d) {
    asm volatile("red.global.add.v4.f32 [%0], {%1, %2, %3, %4};"
                 :: "l"(p), "f"(a), "f"(b), "f"(c), "f"(d) : "memory");
}
__device__ __forceinline__ void red2(float* p, float a, float b) {
    asm volatile("red.global.add.v2.f32 [%0], {%1, %2};"
                 :: "l"(p), "f"(a), "f"(b) : "memory");
}
__device__ __forceinline__ void red1(float* p, float a) {
    asm volatile("red.global.add.f32 [%0], %1;" :: "l"(p), "f"(a) : "memory");
}

// ---------------------------------------------------------------------------
// Per-point splat. q = iz & 3 selects the cheapest vector form per row-pair:
//   q==0 or q==2 : red.v2 (8B aligned, exact payload)   -- 1 transaction/row
//   q==1         : red.v4 window (lanes 1,2 used)       -- 1 transaction/row
//   q==3         : straddles 16B line -> 2 scalar REDs  -- 2 transactions/row
// ---------------------------------------------------------------------------
__device__ __forceinline__ void splat_point(float px, float py, float pz,
                                            float* __restrict__ o) {
    px *= 64.0f; py *= 64.0f; pz *= 64.0f;
    float flx = floorf(px), fly = floorf(py), flz = floorf(pz);
    float dx = px - flx, dy = py - fly, dz = pz - flz;
    float ex = 1.0f - dx, ey = 1.0f - dy, ez = 1.0f - dz;
    int ix = (int)flx + 64, iy = (int)fly + 64, iz = (int)flz + 64;

    if ((unsigned)ix < (unsigned)(DX - 1) &&
        (unsigned)iy < (unsigned)(DY - 1) &&
        (unsigned)iz < (unsigned)(DZ - 1)) {
        int r0 = (ix * DY + iy) * DZ;
        int rows[4] = { r0, r0 + DZ, r0 + DY * DZ, r0 + DY * DZ + DZ };
        float ws[4]  = { ex * ey, ex * dy, dx * ey, dx * dy };

        int q = iz & 3;
        if (q == 3) {
            #pragma unroll
            for (int r = 0; r < 4; r++) {
                red1(o + rows[r] + iz,     ws[r] * ez);
                red1(o + rows[r] + iz + 1, ws[r] * dz);
            }
        } else if (q == 1) {
            int a = iz & ~3;
            #pragma unroll
            for (int r = 0; r < 4; r++)
                red4(o + rows[r] + a, 0.0f, ws[r] * ez, ws[r] * dz, 0.0f);
        } else {  // q == 0 or q == 2: 8B-aligned pair
            #pragma unroll
            for (int r = 0; r < 4; r++)
                red2(o + rows[r] + iz, ws[r] * ez, ws[r] * dz);
        }
    } else {
        // Slow path: per-corner validity (matches reference semantics).
        #pragma unroll
        for (int c = 0; c < 8; c++) {
            int ox = (c >> 2) & 1, oy = (c >> 1) & 1, oz = c & 1;
            int jx = ix + ox, jy = iy + oy, jz = iz + oz;
            if ((unsigned)jx < DX && (unsigned)jy < DY && (unsigned)jz < DZ) {
                float w = (ox ? dx : ex) * (oy ? dy : ey) * (oz ? dz : ez);
                red1(o + ((jx * DY + jy) * DZ + jz), w);
            }
        }
    }
}

// ---------------------------------------------------------------------------
// 2 points per thread (consecutive) for ILP / MLP and fewer warps.
// out layout: [cloud(2)][batch(4)][VOX].
// ---------------------------------------------------------------------------
__global__ void __launch_bounds__(256) splat_kernel(const float* __restrict__ pred,
                                                    const float* __restrict__ gt,
                                                    float* __restrict__ out) {
    int t = blockIdx.x * blockDim.x + threadIdx.x;
    if (t >= NTHREADS_TOTAL) return;
    int p0 = t * PTS_PER_THREAD;

    #pragma unroll
    for (int k = 0; k < PTS_PER_THREAD; k++) {
        int pid = p0 + k;
        int cloud = (pid >= PER_CLOUD) ? 1 : 0;
        int rem = pid - cloud * PER_CLOUD;
        const float* __restrict__ src = cloud ? gt : pred;
        float x = src[rem * 3 + 0];
        float y = src[rem * 3 + 1];
        float z = src[rem * 3 + 2];
        int b = rem >> 18;  // rem / NPTS
        float* __restrict__ o = out + ((size_t)(cloud * BATCH + b)) * VOX;
        splat_point(x, y, z, o);
    }
}

extern "C" void kernel_launch(void* const* d_in, const int* in_sizes, int n_in,
                              void* d_out, int out_size) {
    const float* pred = (const float*)d_in[0];
    const float* gt   = (const float*)d_in[1];
    float* out = (float*)d_out;

    // zero-fill output via memset node (graph-capturable, no alloc)
    cudaMemsetAsync(out, 0, (size_t)out_size * sizeof(float));

    splat_kernel<<<(NTHREADS_TOTAL + 255) / 256, 256>>>(pred, gt, out);
}

// round 4
// speedup vs baseline: 1.0362x; 1.0362x over previous
#include <cuda_runtime.h>
#include <stdint.h>

#define DX 128
#define DY 128
#define DZ 128
#define VOX (DX * DY * DZ)
#define BATCH 4
#define NPTS 262144
#define PER_CLOUD (BATCH * NPTS)
#define TOTAL_PTS (2 * PER_CLOUD)

// ---------------------------------------------------------------------------
// Global float reductions (no-return REDG path).
// ---------------------------------------------------------------------------
__device__ __forceinline__ void red4(float* p, float a, float b, float c, float d) {
    asm volatile("red.global.add.v4.f32 [%0], {%1, %2, %3, %4};"
                 :: "l"(p), "f"(a), "f"(b), "f"(c), "f"(d) : "memory");
}
__device__ __forceinline__ void red1(float* p, float a) {
    asm volatile("red.global.add.f32 [%0], %1;" :: "l"(p), "f"(a) : "memory");
}

// ---------------------------------------------------------------------------
// Trilinear splat: one thread per point (R2 configuration — measured fastest).
// z-pair merged into ONE red.v4 sector transaction when it fits a 16B window
// (q = iz&3 < 3; zero lanes are harmless +0.0 adds). q==3 straddles -> 2 red1.
// out layout: [cloud(2)][batch(4)][VOX] floats.
// ---------------------------------------------------------------------------
__global__ void __launch_bounds__(256) splat_kernel(const float* __restrict__ pred,
                                                    const float* __restrict__ gt,
                                                    float* __restrict__ out) {
    int tid = blockIdx.x * blockDim.x + threadIdx.x;
    if (tid >= TOTAL_PTS) return;

    int cloud = (tid >= PER_CLOUD) ? 1 : 0;
    int rem = tid - cloud * PER_CLOUD;
    const float* __restrict__ src = cloud ? gt : pred;

    float px = src[rem * 3 + 0] * 64.0f;
    float py = src[rem * 3 + 1] * 64.0f;
    float pz = src[rem * 3 + 2] * 64.0f;

    float flx = floorf(px), fly = floorf(py), flz = floorf(pz);
    float dx = px - flx, dy = py - fly, dz = pz - flz;
    float ex = 1.0f - dx, ey = 1.0f - dy, ez = 1.0f - dz;

    int ix = (int)flx + 64;
    int iy = (int)fly + 64;
    int iz = (int)flz + 64;

    int b = rem >> 18;  // rem / NPTS
    float* __restrict__ o = out + ((size_t)(cloud * BATCH + b)) * VOX;

    if ((unsigned)ix < (unsigned)(DX - 1) &&
        (unsigned)iy < (unsigned)(DY - 1) &&
        (unsigned)iz < (unsigned)(DZ - 1)) {
        int r0 = (ix * DY + iy) * DZ;
        int rows[4] = { r0, r0 + DZ, r0 + DY * DZ, r0 + DY * DZ + DZ };
        float ws[4]  = { ex * ey, ex * dy, dx * ey, dx * dy };

        int q = iz & 3;
        int a = iz & ~3;

        if (q < 3) {
            #pragma unroll
            for (int r = 0; r < 4; r++) {
                float lo = ws[r] * ez;
                float hi = ws[r] * dz;
                float v0 = (q == 0) ? lo : 0.0f;
                float v1 = (q == 0) ? hi : ((q == 1) ? lo : 0.0f);
                float v2 = (q == 1) ? hi : ((q == 2) ? lo : 0.0f);
                float v3 = (q == 2) ? hi : 0.0f;
                red4(o + rows[r] + a, v0, v1, v2, v3);
            }
        } else {
            #pragma unroll
            for (int r = 0; r < 4; r++) {
                red1(o + rows[r] + iz,     ws[r] * ez);
                red1(o + rows[r] + iz + 1, ws[r] * dz);
            }
        }
    } else {
        // Slow path: per-corner validity (matches reference semantics).
        #pragma unroll
        for (int c = 0; c < 8; c++) {
            int ox = (c >> 2) & 1, oy = (c >> 1) & 1, oz = c & 1;
            int jx = ix + ox, jy = iy + oy, jz = iz + oz;
            if ((unsigned)jx < DX && (unsigned)jy < DY && (unsigned)jz < DZ) {
                float w = (ox ? dx : ex) * (oy ? dy : ey) * (oz ? dz : ez);
                red1(o + ((jx * DY + jy) * DZ + jz), w);
            }
        }
    }
}

extern "C" void kernel_launch(void* const* d_in, const int* in_sizes, int n_in,
                              void* d_out, int out_size) {
    const float* pred = (const float*)d_in[0];
    const float* gt   = (const float*)d_in[1];
    float* out = (float*)d_out;

    // zero-fill output via memset node (graph-capturable, no alloc)
    cudaMemsetAsync(out, 0, (size_t)out_size * sizeof(float));

    splat_kernel<<<(TOTAL_PTS + 255) / 256, 256>>>(pred, gt, out);
}